// round 8
// baseline (speedup 1.0000x reference)
#include <cuda_runtime.h>
#include <cuda_bf16.h>
#include <cstdint>

#define B_TOT 4096
#define B_HALF 2048
#define PAD 130

// ---------------- device scratch ----------------
__device__ float g_zt[B_TOT * 64];
__device__ float g_s[B_TOT];
__device__ float g_e[B_TOT];
__device__ float g_T[2];
__device__ float g_Z[128];
__device__ float g_diag[B_TOT];
__device__ float g_pM[32 * B_TOT];
__device__ float g_pS[32 * B_TOT];
__device__ double g_bsum[32];
__device__ __align__(16) unsigned short g_A[B_TOT * 384];  // bf16 [hi|lo|hi]
__device__ __align__(16) unsigned short g_B[B_TOT * 384];  // bf16 [hi|hi|lo]

__device__ __forceinline__ uint32_t smem_u32(const void* p) {
    uint32_t a;
    asm("{ .reg .u64 t; cvta.to.shared.u64 t, %1; cvt.u32.u64 %0, t; }"
        : "=r"(a) : "l"(p));
    return a;
}
__device__ __forceinline__ void ffma2(unsigned long long& d,
                                      unsigned long long a,
                                      unsigned long long b) {
    asm("fma.rn.f32x2 %0, %1, %2, %0;" : "+l"(d) : "l"(a), "l"(b));
}

// ---------------- K1: zt/score + A-side bf16 split ------------------------
// 512 blocks x 8 rows.
__global__ void __launch_bounds__(128) k_zt_s(
    const float* __restrict__ zw0, const float* __restrict__ zw1,
    const float* __restrict__ l0w, const float* __restrict__ l0b,
    const float* __restrict__ l1w, const float* __restrict__ l1b,
    const float* __restrict__ a01w, const float* __restrict__ a01b,
    const float* __restrict__ a02w, const float* __restrict__ a02b,
    const float* __restrict__ a11w, const float* __restrict__ a11b,
    const float* __restrict__ a12w, const float* __restrict__ a12b)
{
    __shared__ float lw_s[64 * 132];
    __shared__ float awT[64 * 32];
    __shared__ float lb_s[64], ab_s[32], a2_s[32];
    __shared__ float zw_s[2][128];
    __shared__ float zt_s[2][64];
    __shared__ float a2b_s;
    int tid = threadIdx.x;
    int row0 = blockIdx.x * 8;
    int g = (row0 >= B_HALF);
    const float* zw  = g ? (zw1 + (row0 - B_HALF) * 128) : (zw0 + row0 * 128);
    const float* lw  = g ? l1w : l0w;
    const float* lb  = g ? l1b : l0b;
    const float* a1w = g ? a11w : a01w;
    const float* a1b = g ? a11b : a01b;
    const float* a2w = g ? a12w : a02w;
    const float* a2b = g ? a12b : a02b;

    // A-side bf16 error-compensated split for this block's 8 zw rows
    for (int n = tid; n < 1024; n += 128) {
        int r = n >> 7, col = n & 127;
        float x = zw[r * 128 + col];
        __nv_bfloat16 h = __float2bfloat16(x);
        __nv_bfloat16 l = __float2bfloat16(x - __bfloat162float(h));
        unsigned short hu = __bfloat16_as_ushort(h);
        unsigned short lu = __bfloat16_as_ushort(l);
        unsigned short* Ad = g_A + (size_t)(row0 + r) * 384;
        Ad[col] = hu; Ad[128 + col] = lu; Ad[256 + col] = hu;
    }

    for (int n = tid; n < 2048; n += 128) {
        float4 v = ((const float4*)lw)[n];
        int t = n >> 5; int k4 = (n & 31) * 4;
        *((float4*)&lw_s[t * 132 + k4]) = v;
    }
    for (int n = tid; n < 512; n += 128) {
        float4 v = ((const float4*)a1w)[n];
        int t = n >> 4; int k = (n & 15) * 4;
        awT[(k + 0) * 32 + t] = v.x; awT[(k + 1) * 32 + t] = v.y;
        awT[(k + 2) * 32 + t] = v.z; awT[(k + 3) * 32 + t] = v.w;
    }
    if (tid < 64) lb_s[tid] = lb[tid];
    if (tid < 32) { ab_s[tid] = a1b[tid]; a2_s[tid] = a2w[tid]; }
    if (tid == 0) a2b_s = a2b[0];
    __syncthreads();

    for (int rp = 0; rp < 8; rp += 2) {
        ((float*)zw_s)[tid]       = zw[rp * 128 + tid];
        ((float*)zw_s)[tid + 128] = zw[rp * 128 + tid + 128];
        __syncthreads();
        int t = tid & 63, rs = tid >> 6;
        float acc = lb_s[t];
        #pragma unroll
        for (int k = 0; k < 128; k += 4) {
            float4 w = *((const float4*)&lw_s[t * 132 + k]);
            float4 z = *((const float4*)&zw_s[rs][k]);
            acc += w.x * z.x + w.y * z.y + w.z * z.z + w.w * z.w;
        }
        float zt = fmaxf(acc, 0.0f);
        zt_s[rs][t] = zt;
        g_zt[(row0 + rp + rs) * 64 + t] = zt;
        __syncthreads();
        if (tid < 64) {
            int r = tid >> 5, j = tid & 31;
            float h = ab_s[j];
            #pragma unroll
            for (int k = 0; k < 64; k++) h += zt_s[r][k] * awT[k * 32 + j];
            h = tanhf(h);
            float v = h * a2_s[j];
            #pragma unroll
            for (int o = 16; o; o >>= 1) v += __shfl_xor_sync(0xffffffffu, v, o);
            if (j == 0) g_s[row0 + rp + r] = v + a2b_s;
        }
        __syncthreads();
    }
}

// ---------------- K2: per-group m, e, T, Z (fully fused) ------------------
__global__ void __launch_bounds__(1024) k_stats2() {
    __shared__ float red[1024];
    __shared__ float es[2048];
    int g = blockIdx.x;
    int base = g * B_HALF;
    int tid = threadIdx.x;
    float s0 = g_s[base + tid], s1 = g_s[base + tid + 1024];
    float m = fmaxf(s0, s1);
    red[tid] = m; __syncthreads();
    for (int s = 512; s > 0; s >>= 1) {
        if (tid < s) red[tid] = fmaxf(red[tid], red[tid + s]);
        __syncthreads();
    }
    m = red[0];
    __syncthreads();
    float e0 = __expf(s0 - m);
    float e1 = __expf(s1 - m);
    g_e[base + tid] = e0; g_e[base + tid + 1024] = e1;
    es[tid] = e0; es[tid + 1024] = e1;
    red[tid] = e0 + e1; __syncthreads();
    for (int s = 512; s > 0; s >>= 1) {
        if (tid < s) red[tid] += red[tid + s];
        __syncthreads();
    }
    if (tid == 0) g_T[g] = red[0];
    __syncthreads();
    // Z[d] = sum_r e_r * zt[r][d], 64 dims x 16 subs
    int d = tid & 63, sub = tid >> 6;
    float z = 0.f;
    #pragma unroll 4
    for (int r = sub; r < B_HALF; r += 16)
        z += es[r] * g_zt[(base + r) * 64 + d];
    red[tid] = z; __syncthreads();
    if (sub < 8) red[tid] += red[tid + 512];
    __syncthreads();
    if (sub < 4) red[tid] += red[tid + 256];
    __syncthreads();
    if (sub < 2) red[tid] += red[tid + 128];
    __syncthreads();
    if (sub == 0) g_Z[g * 64 + d] = red[tid] + red[tid + 64];
}

// ---------------- K3: build u + pred GEMM + bf16 B-split ------------------
// 32 blocks x 256 threads; 128x128 output tile, K=128 (FFMA2).
__global__ void __launch_bounds__(256) k_pred_gemm(
    const float* __restrict__ c,
    const float* __restrict__ Wkw, const float* __restrict__ Wkb,
    const float* __restrict__ Ww0w, const float* __restrict__ Ww0b,
    const float* __restrict__ Ww1w, const float* __restrict__ Ww1b)
{
    extern __shared__ float sm[];
    float* As   = sm;                      // [128][130]
    float* Bs   = sm + 128 * PAD;          // [128][130]
    float* bias = sm + 2 * 128 * PAD;      // [128]
    float* Zs   = bias + 128;              // [64]
    float* es   = Zs + 64;                 // [128]
    float* invs = es + 128;                // [128]
    int tid = threadIdx.x;
    int row0 = blockIdx.x * 128;
    int g = (row0 >= B_HALF);
    const float* Ww = g ? Ww1w : Ww0w;
    const float* Wb = g ? Ww1b : Ww0b;

    // weights, bias, Z, e, 1/(T-e)
    for (int n = tid; n < 4096; n += 256) {
        int j = n >> 5, q = n & 31;
        float4 w; int off;
        if (q < 16) { w = ((const float4*)Ww)[j * 16 + q];         off = q * 4; }
        else        { w = ((const float4*)Wkw)[j * 16 + (q - 16)]; off = 64 + (q - 16) * 4; }
        *(float2*)&Bs[j * PAD + off]     = make_float2(w.x, w.y);
        *(float2*)&Bs[j * PAD + off + 2] = make_float2(w.z, w.w);
    }
    if (tid < 128) {
        bias[tid] = Wb[tid] + Wkb[tid];
        float e = g_e[row0 + tid];
        es[tid] = e;
        invs[tid] = 1.0f / (g_T[g] - e);
    }
    if (tid < 64) Zs[tid] = g_Z[g * 64 + tid];
    __syncthreads();

    // build u = [pooled | c] directly into As
    for (int n = tid; n < 4096; n += 256) {
        int r = n >> 5, c4 = (n & 31) * 4;
        float4 v;
        if (c4 < 64) {
            float4 zt4 = *(const float4*)&g_zt[(row0 + r) * 64 + c4];
            float e = es[r], inv = invs[r];
            v.x = (Zs[c4 + 0] - e * zt4.x) * inv;
            v.y = (Zs[c4 + 1] - e * zt4.y) * inv;
            v.z = (Zs[c4 + 2] - e * zt4.z) * inv;
            v.w = (Zs[c4 + 3] - e * zt4.w) * inv;
        } else {
            v = *(const float4*)&c[(row0 + r) * 64 + (c4 - 64)];
        }
        *(float2*)&As[r * PAD + c4]     = make_float2(v.x, v.y);
        *(float2*)&As[r * PAD + c4 + 2] = make_float2(v.z, v.w);
    }
    __syncthreads();

    int tx = tid & 15, ty = tid >> 4;
    unsigned long long acc2[8][8];
    #pragma unroll
    for (int i = 0; i < 8; i++)
        #pragma unroll
        for (int j = 0; j < 8; j++) acc2[i][j] = 0ull;
    const float* arow = As + ty * PAD;
    const float* brow = Bs + tx * PAD;
    #pragma unroll 2
    for (int k = 0; k < 128; k += 2) {
        unsigned long long a[8], b[8];
        #pragma unroll
        for (int i = 0; i < 8; i++)
            a[i] = *((const unsigned long long*)&arow[i * 16 * PAD + k]);
        #pragma unroll
        for (int j = 0; j < 8; j++)
            b[j] = *((const unsigned long long*)&brow[j * 16 * PAD + k]);
        #pragma unroll
        for (int i = 0; i < 8; i++)
            #pragma unroll
            for (int j = 0; j < 8; j++)
                ffma2(acc2[i][j], a[i], b[j]);
    }
    // epilogue: pred -> bf16 [hi|hi|lo] straight into g_B
    #pragma unroll
    for (int i = 0; i < 8; i++) {
        int row = row0 + ty + 16 * i;
        #pragma unroll
        for (int j = 0; j < 8; j++) {
            int col = tx + 16 * j;
            unsigned long long u = acc2[i][j];
            float lo = __uint_as_float((unsigned)u);
            float hi = __uint_as_float((unsigned)(u >> 32));
            float p = lo + hi + bias[col];
            __nv_bfloat16 h = __float2bfloat16(p);
            __nv_bfloat16 l = __float2bfloat16(p - __bfloat162float(h));
            unsigned short hu = __bfloat16_as_ushort(h);
            unsigned short lu = __bfloat16_as_ushort(l);
            unsigned short* Bd = g_B + (size_t)row * 384;
            Bd[col] = hu; Bd[128 + col] = hu; Bd[256 + col] = lu;
        }
    }
}

// ---------------- K4: HMMA bf16 GEMM (K'=384) + fused LSE partials -------
#define KC 64
#define NCHUNK 6
#define ROWB 144
#define ABUF 18432
#define SM_A0 0
#define SM_B0 36864
#define SM_RED 73728
#define GSMEM (73728 + 4096)

__global__ void __launch_bounds__(256) k_gemm_mma() {
    extern __shared__ __align__(128) char smem[];
    uint32_t sb = smem_u32(smem);
    int tid = threadIdx.x, wid = tid >> 5, lane = tid & 31;
    int cb = blockIdx.x, rb = blockIdx.y;
    int wr = wid >> 2, wc = wid & 3;
    const unsigned short* asrc = g_A + (size_t)rb * 128 * 384;
    const unsigned short* bsrc = g_B + (size_t)cb * 128 * 384;

    float acc[4][4][4];
    #pragma unroll
    for (int i = 0; i < 4; i++)
        #pragma unroll
        for (int j = 0; j < 4; j++)
            #pragma unroll
            for (int q = 0; q < 4; q++) acc[i][j][q] = 0.f;

    #define PREFETCH(c, buf) do {                                              \
        const unsigned short* _ap = asrc + (c) * KC;                           \
        const unsigned short* _bp = bsrc + (c) * KC;                           \
        _Pragma("unroll")                                                      \
        for (int _i = 0; _i < 4; _i++) {                                       \
            int _idx = tid + _i * 256;                                         \
            int _row = _idx >> 3, _kc = _idx & 7;                              \
            uint32_t _da = sb + SM_A0 + (buf) * ABUF + _row * ROWB + _kc * 16; \
            asm volatile("cp.async.cg.shared.global [%0], [%1], 16;"           \
                :: "r"(_da), "l"(_ap + _row * 384 + _kc * 8));                 \
            uint32_t _db = sb + SM_B0 + (buf) * ABUF + _row * ROWB + _kc * 16; \
            asm volatile("cp.async.cg.shared.global [%0], [%1], 16;"           \
                :: "r"(_db), "l"(_bp + _row * 384 + _kc * 8));                 \
        }                                                                      \
        asm volatile("cp.async.commit_group;");                                \
    } while (0)

    int arow = lane & 15, ahalf = lane >> 4;
    int brow = lane & 7,  bhalf = (lane >> 3) & 1;

    PREFETCH(0, 0);
    for (int c = 0; c < NCHUNK; c++) {
        int buf = c & 1;
        if (c + 1 < NCHUNK) {
            PREFETCH(c + 1, buf ^ 1);
            asm volatile("cp.async.wait_group 1;");
        } else {
            asm volatile("cp.async.wait_group 0;");
        }
        __syncthreads();
        uint32_t abase = sb + SM_A0 + buf * ABUF;
        uint32_t bbase = sb + SM_B0 + buf * ABUF;
        #pragma unroll
        for (int k0 = 0; k0 < KC; k0 += 16) {
            uint32_t a[4][4], b[4][2];
            #pragma unroll
            for (int mi = 0; mi < 4; mi++) {
                uint32_t ad = abase + (wr * 64 + mi * 16 + arow) * ROWB
                            + (k0 + 8 * ahalf) * 2;
                asm volatile("ldmatrix.sync.aligned.m8n8.x4.shared.b16 "
                             "{%0,%1,%2,%3}, [%4];"
                    : "=r"(a[mi][0]), "=r"(a[mi][1]),
                      "=r"(a[mi][2]), "=r"(a[mi][3]) : "r"(ad));
            }
            #pragma unroll
            for (int nj = 0; nj < 4; nj++) {
                uint32_t bd = bbase + (wc * 32 + nj * 8 + brow) * ROWB
                            + (k0 + 8 * bhalf) * 2;
                asm volatile("ldmatrix.sync.aligned.m8n8.x2.shared.b16 "
                             "{%0,%1}, [%2];"
                    : "=r"(b[nj][0]), "=r"(b[nj][1]) : "r"(bd));
            }
            #pragma unroll
            for (int mi = 0; mi < 4; mi++)
                #pragma unroll
                for (int nj = 0; nj < 4; nj++)
                    asm volatile(
                        "mma.sync.aligned.m16n8k16.row.col.f32.bf16.bf16.f32 "
                        "{%0,%1,%2,%3}, {%4,%5,%6,%7}, {%8,%9}, {%0,%1,%2,%3};"
                        : "+f"(acc[mi][nj][0]), "+f"(acc[mi][nj][1]),
                          "+f"(acc[mi][nj][2]), "+f"(acc[mi][nj][3])
                        : "r"(a[mi][0]), "r"(a[mi][1]),
                          "r"(a[mi][2]), "r"(a[mi][3]),
                          "r"(b[nj][0]), "r"(b[nj][1]));
        }
        __syncthreads();
    }

    float* pMs = (float*)(smem + SM_RED);
    float* pSs = pMs + 512;
    int r4 = lane >> 2;
    #pragma unroll
    for (int mi = 0; mi < 4; mi++) {
        #pragma unroll
        for (int half = 0; half < 2; half++) {
            float m = -1e30f;
            #pragma unroll
            for (int nj = 0; nj < 4; nj++) {
                m = fmaxf(m, acc[mi][nj][half * 2]);
                m = fmaxf(m, acc[mi][nj][half * 2 + 1]);
            }
            m = fmaxf(m, __shfl_xor_sync(0xffffffffu, m, 1));
            m = fmaxf(m, __shfl_xor_sync(0xffffffffu, m, 2));
            float s = 0.f;
            #pragma unroll
            for (int nj = 0; nj < 4; nj++)
                s += __expf(acc[mi][nj][half * 2] - m)
                   + __expf(acc[mi][nj][half * 2 + 1] - m);
            s += __shfl_xor_sync(0xffffffffu, s, 1);
            s += __shfl_xor_sync(0xffffffffu, s, 2);
            if ((lane & 3) == 0) {
                int lr = wr * 64 + mi * 16 + half * 8 + r4;
                pMs[lr * 4 + wc] = m;
                pSs[lr * 4 + wc] = s;
            }
        }
    }
    if (rb == cb) {
        int c2 = (lane & 3) * 2;
        #pragma unroll
        for (int mi = 0; mi < 4; mi++)
            #pragma unroll
            for (int nj = 0; nj < 4; nj++)
                #pragma unroll
                for (int q = 0; q < 4; q++) {
                    int lr = wr * 64 + mi * 16 + (q >> 1) * 8 + r4;
                    int lc = wc * 32 + nj * 8 + c2 + (q & 1);
                    if (lr == lc) g_diag[rb * 128 + lr] = acc[mi][nj][q];
                }
    }
    __syncthreads();
    if (tid < 128) {
        float M = fmaxf(fmaxf(pMs[tid * 4], pMs[tid * 4 + 1]),
                        fmaxf(pMs[tid * 4 + 2], pMs[tid * 4 + 3]));
        float S = 0.f;
        #pragma unroll
        for (int w = 0; w < 4; w++)
            S += pSs[tid * 4 + w] * __expf(pMs[tid * 4 + w] - M);
        int grow = rb * 128 + tid;
        g_pM[cb * B_TOT + grow] = M;
        g_pS[cb * B_TOT + grow] = S;
    }
}

// ---------------- K5: combine partials + per-block double sum -------------
__global__ void __launch_bounds__(128) k_combine() {
    __shared__ double red[128];
    int tid = threadIdx.x;
    int i = blockIdx.x * 128 + tid;
    float M = -1e30f;
    #pragma unroll
    for (int p = 0; p < 32; p++) M = fmaxf(M, g_pM[p * B_TOT + i]);
    float S = 0.f;
    #pragma unroll
    for (int p = 0; p < 32; p++)
        S += g_pS[p * B_TOT + i] * __expf(g_pM[p * B_TOT + i] - M);
    red[tid] = (double)(M + logf(S) - g_diag[i]);
    __syncthreads();
    for (int s = 64; s > 0; s >>= 1) {
        if (tid < s) red[tid] += red[tid + s];
        __syncthreads();
    }
    if (tid == 0) g_bsum[blockIdx.x] = red[0];
}

// ---------------- K6: final 32-way sum ------------------------------------
__global__ void k_final(float* __restrict__ out) {
    if (threadIdx.x == 0) {
        double s = 0.0;
        #pragma unroll
        for (int i = 0; i < 32; i++) s += g_bsum[i];
        out[0] = (float)(s / 4096.0);
    }
}

extern "C" void kernel_launch(void* const* d_in, const int* in_sizes, int n_in,
                              void* d_out, int out_size) {
    const float* zw0  = (const float*)d_in[0];
    const float* zw1  = (const float*)d_in[1];
    const float* c    = (const float*)d_in[2];
    const float* Wkw  = (const float*)d_in[3];
    const float* Wkb  = (const float*)d_in[4];
    const float* Ww0w = (const float*)d_in[5];
    const float* Ww0b = (const float*)d_in[6];
    const float* Ww1w = (const float*)d_in[7];
    const float* Ww1b = (const float*)d_in[8];
    const float* l0w  = (const float*)d_in[9];
    const float* l0b  = (const float*)d_in[10];
    const float* l1w  = (const float*)d_in[11];
    const float* l1b  = (const float*)d_in[12];
    const float* a01w = (const float*)d_in[13];
    const float* a01b = (const float*)d_in[14];
    const float* a02w = (const float*)d_in[15];
    const float* a02b = (const float*)d_in[16];
    const float* a11w = (const float*)d_in[17];
    const float* a11b = (const float*)d_in[18];
    const float* a12w = (const float*)d_in[19];
    const float* a12b = (const float*)d_in[20];
    float* out = (float*)d_out;

    int predsm = (2 * 128 * PAD + 128 + 64 + 128 + 128) * 4;
    cudaFuncSetAttribute(k_pred_gemm, cudaFuncAttributeMaxDynamicSharedMemorySize,
                         predsm);
    cudaFuncSetAttribute(k_gemm_mma, cudaFuncAttributeMaxDynamicSharedMemorySize,
                         GSMEM);

    k_zt_s<<<512, 128>>>(zw0, zw1, l0w, l0b, l1w, l1b,
                         a01w, a01b, a02w, a02b, a11w, a11b, a12w, a12b);
    k_stats2<<<2, 1024>>>();
    k_pred_gemm<<<32, 256, predsm>>>(c, Wkw, Wkb, Ww0w, Ww0b, Ww1w, Ww1b);
    k_gemm_mma<<<dim3(32, 32), 256, GSMEM>>>();
    k_combine<<<32, 128>>>();
    k_final<<<1, 32>>>(out);
}

// round 10
// speedup vs baseline: 1.0164x; 1.0164x over previous
#include <cuda_runtime.h>
#include <cuda_bf16.h>
#include <cstdint>

#define B_TOT 4096
#define B_HALF 2048
#define PAD 130

// ---------------- device scratch ----------------
__device__ float g_zt[B_TOT * 64];
__device__ float g_s[B_TOT];
__device__ float g_e[B_TOT];
__device__ float g_T[2];
__device__ float g_Z[128];
__device__ float g_diag[B_TOT];
__device__ float g_pM[32 * B_TOT];
__device__ float g_pS[32 * B_TOT];
__device__ double g_bsum[32];
__device__ __align__(16) unsigned short g_A[B_TOT * 384];  // bf16 [hi|lo|hi]
__device__ __align__(16) unsigned short g_B[B_TOT * 384];  // bf16 [hi|hi|lo]

__device__ __forceinline__ uint32_t smem_u32(const void* p) {
    uint32_t a;
    asm("{ .reg .u64 t; cvta.to.shared.u64 t, %1; cvt.u32.u64 %0, t; }"
        : "=r"(a) : "l"(p));
    return a;
}
__device__ __forceinline__ void ffma2(unsigned long long& d,
                                      unsigned long long a,
                                      unsigned long long b) {
    asm("fma.rn.f32x2 %0, %1, %2, %0;" : "+l"(d) : "l"(a), "l"(b));
}

// ---------------- K1: zt/score + A-side bf16 split ------------------------
__global__ void __launch_bounds__(128) k_zt_s(
    const float* __restrict__ zw0, const float* __restrict__ zw1,
    const float* __restrict__ l0w, const float* __restrict__ l0b,
    const float* __restrict__ l1w, const float* __restrict__ l1b,
    const float* __restrict__ a01w, const float* __restrict__ a01b,
    const float* __restrict__ a02w, const float* __restrict__ a02b,
    const float* __restrict__ a11w, const float* __restrict__ a11b,
    const float* __restrict__ a12w, const float* __restrict__ a12b)
{
    __shared__ float lw_s[64 * 132];
    __shared__ float awT[64 * 32];
    __shared__ float lb_s[64], ab_s[32], a2_s[32];
    __shared__ float zw_s[2][128];
    __shared__ float zt_s[2][64];
    __shared__ float a2b_s;
    int tid = threadIdx.x;
    int row0 = blockIdx.x * 8;
    int g = (row0 >= B_HALF);
    const float* zw  = g ? (zw1 + (row0 - B_HALF) * 128) : (zw0 + row0 * 128);
    const float* lw  = g ? l1w : l0w;
    const float* lb  = g ? l1b : l0b;
    const float* a1w = g ? a11w : a01w;
    const float* a1b = g ? a11b : a01b;
    const float* a2w = g ? a12w : a02w;
    const float* a2b = g ? a12b : a02b;

    for (int n = tid; n < 1024; n += 128) {
        int r = n >> 7, col = n & 127;
        float x = zw[r * 128 + col];
        __nv_bfloat16 h = __float2bfloat16(x);
        __nv_bfloat16 l = __float2bfloat16(x - __bfloat162float(h));
        unsigned short hu = __bfloat16_as_ushort(h);
        unsigned short lu = __bfloat16_as_ushort(l);
        unsigned short* Ad = g_A + (size_t)(row0 + r) * 384;
        Ad[col] = hu; Ad[128 + col] = lu; Ad[256 + col] = hu;
    }

    for (int n = tid; n < 2048; n += 128) {
        float4 v = ((const float4*)lw)[n];
        int t = n >> 5; int k4 = (n & 31) * 4;
        *((float4*)&lw_s[t * 132 + k4]) = v;
    }
    for (int n = tid; n < 512; n += 128) {
        float4 v = ((const float4*)a1w)[n];
        int t = n >> 4; int k = (n & 15) * 4;
        awT[(k + 0) * 32 + t] = v.x; awT[(k + 1) * 32 + t] = v.y;
        awT[(k + 2) * 32 + t] = v.z; awT[(k + 3) * 32 + t] = v.w;
    }
    if (tid < 64) lb_s[tid] = lb[tid];
    if (tid < 32) { ab_s[tid] = a1b[tid]; a2_s[tid] = a2w[tid]; }
    if (tid == 0) a2b_s = a2b[0];
    __syncthreads();

    for (int rp = 0; rp < 8; rp += 2) {
        ((float*)zw_s)[tid]       = zw[rp * 128 + tid];
        ((float*)zw_s)[tid + 128] = zw[rp * 128 + tid + 128];
        __syncthreads();
        int t = tid & 63, rs = tid >> 6;
        float acc = lb_s[t];
        #pragma unroll
        for (int k = 0; k < 128; k += 4) {
            float4 w = *((const float4*)&lw_s[t * 132 + k]);
            float4 z = *((const float4*)&zw_s[rs][k]);
            acc += w.x * z.x + w.y * z.y + w.z * z.z + w.w * z.w;
        }
        float zt = fmaxf(acc, 0.0f);
        zt_s[rs][t] = zt;
        g_zt[(row0 + rp + rs) * 64 + t] = zt;
        __syncthreads();
        if (tid < 64) {
            int r = tid >> 5, j = tid & 31;
            float h = ab_s[j];
            #pragma unroll
            for (int k = 0; k < 64; k++) h += zt_s[r][k] * awT[k * 32 + j];
            h = tanhf(h);
            float v = h * a2_s[j];
            #pragma unroll
            for (int o = 16; o; o >>= 1) v += __shfl_xor_sync(0xffffffffu, v, o);
            if (j == 0) g_s[row0 + rp + r] = v + a2b_s;
        }
        __syncthreads();
    }
}

// ---------------- K2: per-group m, e, T, Z (fully fused) ------------------
__global__ void __launch_bounds__(1024) k_stats2() {
    __shared__ float red[1024];
    __shared__ float es[2048];
    int g = blockIdx.x;
    int base = g * B_HALF;
    int tid = threadIdx.x;
    float s0 = g_s[base + tid], s1 = g_s[base + tid + 1024];
    float m = fmaxf(s0, s1);
    red[tid] = m; __syncthreads();
    for (int s = 512; s > 0; s >>= 1) {
        if (tid < s) red[tid] = fmaxf(red[tid], red[tid + s]);
        __syncthreads();
    }
    m = red[0];
    __syncthreads();
    float e0 = __expf(s0 - m);
    float e1 = __expf(s1 - m);
    g_e[base + tid] = e0; g_e[base + tid + 1024] = e1;
    es[tid] = e0; es[tid + 1024] = e1;
    red[tid] = e0 + e1; __syncthreads();
    for (int s = 512; s > 0; s >>= 1) {
        if (tid < s) red[tid] += red[tid + s];
        __syncthreads();
    }
    if (tid == 0) g_T[g] = red[0];
    __syncthreads();
    int d = tid & 63, sub = tid >> 6;
    float z = 0.f;
    #pragma unroll 4
    for (int r = sub; r < B_HALF; r += 16)
        z += es[r] * g_zt[(base + r) * 64 + d];
    red[tid] = z; __syncthreads();
    if (sub < 8) red[tid] += red[tid + 512];
    __syncthreads();
    if (sub < 4) red[tid] += red[tid + 256];
    __syncthreads();
    if (sub < 2) red[tid] += red[tid + 128];
    __syncthreads();
    if (sub == 0) g_Z[g * 64 + d] = red[tid] + red[tid + 64];
}

// ---------------- K3: build u + pred GEMM + bf16 B-split ------------------
__global__ void __launch_bounds__(256) k_pred_gemm(
    const float* __restrict__ c,
    const float* __restrict__ Wkw, const float* __restrict__ Wkb,
    const float* __restrict__ Ww0w, const float* __restrict__ Ww0b,
    const float* __restrict__ Ww1w, const float* __restrict__ Ww1b)
{
    extern __shared__ float sm[];
    float* As   = sm;
    float* Bs   = sm + 128 * PAD;
    float* bias = sm + 2 * 128 * PAD;
    float* Zs   = bias + 128;
    float* es   = Zs + 64;
    float* invs = es + 128;
    int tid = threadIdx.x;
    int row0 = blockIdx.x * 128;
    int g = (row0 >= B_HALF);
    const float* Ww = g ? Ww1w : Ww0w;
    const float* Wb = g ? Ww1b : Ww0b;

    for (int n = tid; n < 4096; n += 256) {
        int j = n >> 5, q = n & 31;
        float4 w; int off;
        if (q < 16) { w = ((const float4*)Ww)[j * 16 + q];         off = q * 4; }
        else        { w = ((const float4*)Wkw)[j * 16 + (q - 16)]; off = 64 + (q - 16) * 4; }
        *(float2*)&Bs[j * PAD + off]     = make_float2(w.x, w.y);
        *(float2*)&Bs[j * PAD + off + 2] = make_float2(w.z, w.w);
    }
    if (tid < 128) {
        bias[tid] = Wb[tid] + Wkb[tid];
        float e = g_e[row0 + tid];
        es[tid] = e;
        invs[tid] = 1.0f / (g_T[g] - e);
    }
    if (tid < 64) Zs[tid] = g_Z[g * 64 + tid];
    __syncthreads();

    for (int n = tid; n < 4096; n += 256) {
        int r = n >> 5, c4 = (n & 31) * 4;
        float4 v;
        if (c4 < 64) {
            float4 zt4 = *(const float4*)&g_zt[(row0 + r) * 64 + c4];
            float e = es[r], inv = invs[r];
            v.x = (Zs[c4 + 0] - e * zt4.x) * inv;
            v.y = (Zs[c4 + 1] - e * zt4.y) * inv;
            v.z = (Zs[c4 + 2] - e * zt4.z) * inv;
            v.w = (Zs[c4 + 3] - e * zt4.w) * inv;
        } else {
            v = *(const float4*)&c[(row0 + r) * 64 + (c4 - 64)];
        }
        *(float2*)&As[r * PAD + c4]     = make_float2(v.x, v.y);
        *(float2*)&As[r * PAD + c4 + 2] = make_float2(v.z, v.w);
    }
    __syncthreads();

    int tx = tid & 15, ty = tid >> 4;
    unsigned long long acc2[8][8];
    #pragma unroll
    for (int i = 0; i < 8; i++)
        #pragma unroll
        for (int j = 0; j < 8; j++) acc2[i][j] = 0ull;
    const float* arow = As + ty * PAD;
    const float* brow = Bs + tx * PAD;
    #pragma unroll 2
    for (int k = 0; k < 128; k += 2) {
        unsigned long long a[8], b[8];
        #pragma unroll
        for (int i = 0; i < 8; i++)
            a[i] = *((const unsigned long long*)&arow[i * 16 * PAD + k]);
        #pragma unroll
        for (int j = 0; j < 8; j++)
            b[j] = *((const unsigned long long*)&brow[j * 16 * PAD + k]);
        #pragma unroll
        for (int i = 0; i < 8; i++)
            #pragma unroll
            for (int j = 0; j < 8; j++)
                ffma2(acc2[i][j], a[i], b[j]);
    }
    #pragma unroll
    for (int i = 0; i < 8; i++) {
        int row = row0 + ty + 16 * i;
        #pragma unroll
        for (int j = 0; j < 8; j++) {
            int col = tx + 16 * j;
            unsigned long long u = acc2[i][j];
            float lo = __uint_as_float((unsigned)u);
            float hi = __uint_as_float((unsigned)(u >> 32));
            float p = lo + hi + bias[col];
            __nv_bfloat16 h = __float2bfloat16(p);
            __nv_bfloat16 l = __float2bfloat16(p - __bfloat162float(h));
            unsigned short hu = __bfloat16_as_ushort(h);
            unsigned short lu = __bfloat16_as_ushort(l);
            unsigned short* Bd = g_B + (size_t)row * 384;
            Bd[col] = hu; Bd[128 + col] = hu; Bd[256 + col] = lu;
        }
    }
}

// ---------------- K4: HMMA bf16 GEMM (K'=384) + fused LSE partials -------
// 128x128 block tile, 4 warps of 64x64, mma.m16n8k16, cp.async double buffer.
#define KC 64
#define NCHUNK 6
#define ROWB 144
#define ABUF 18432
#define SM_A0 0
#define SM_B0 36864
#define SM_RED 73728
#define GSMEM (73728 + 2048)

__global__ void __launch_bounds__(128, 2) k_gemm_mma() {
    extern __shared__ __align__(128) char smem[];
    uint32_t sb = smem_u32(smem);
    int tid = threadIdx.x, wid = tid >> 5, lane = tid & 31;
    int cb = blockIdx.x, rb = blockIdx.y;
    int wr = wid >> 1, wc = wid & 1;      // warp tile: rows wr*64, cols wc*64
    const unsigned short* asrc = g_A + (size_t)rb * 128 * 384;
    const unsigned short* bsrc = g_B + (size_t)cb * 128 * 384;

    float acc[4][8][4];
    #pragma unroll
    for (int i = 0; i < 4; i++)
        #pragma unroll
        for (int j = 0; j < 8; j++)
            #pragma unroll
            for (int q = 0; q < 4; q++) acc[i][j][q] = 0.f;

    #define PREFETCH(c, buf) do {                                              \
        const unsigned short* _ap = asrc + (c) * KC;                           \
        const unsigned short* _bp = bsrc + (c) * KC;                           \
        _Pragma("unroll")                                                      \
        for (int _i = 0; _i < 8; _i++) {                                       \
            int _idx = tid + _i * 128;                                         \
            int _row = _idx >> 3, _kc = _idx & 7;                              \
            uint32_t _da = sb + SM_A0 + (buf) * ABUF + _row * ROWB + _kc * 16; \
            asm volatile("cp.async.cg.shared.global [%0], [%1], 16;"           \
                :: "r"(_da), "l"(_ap + _row * 384 + _kc * 8));                 \
            uint32_t _db = sb + SM_B0 + (buf) * ABUF + _row * ROWB + _kc * 16; \
            asm volatile("cp.async.cg.shared.global [%0], [%1], 16;"           \
                :: "r"(_db), "l"(_bp + _row * 384 + _kc * 8));                 \
        }                                                                      \
        asm volatile("cp.async.commit_group;");                                \
    } while (0)

    int arow = lane & 15, ahalf = lane >> 4;
    int bnoff = (lane >> 4) & 1;          // which n8 of the pair
    int bkhalf = (lane >> 3) & 1;         // which k-half
    int brow = lane & 7;

    PREFETCH(0, 0);
    for (int c = 0; c < NCHUNK; c++) {
        int buf = c & 1;
        if (c + 1 < NCHUNK) {
            PREFETCH(c + 1, buf ^ 1);
            asm volatile("cp.async.wait_group 1;");
        } else {
            asm volatile("cp.async.wait_group 0;");
        }
        __syncthreads();
        uint32_t abase = sb + SM_A0 + buf * ABUF;
        uint32_t bbase = sb + SM_B0 + buf * ABUF;
        #pragma unroll
        for (int k0 = 0; k0 < KC; k0 += 16) {
            uint32_t a[4][4], b[4][4];
            #pragma unroll
            for (int mi = 0; mi < 4; mi++) {
                uint32_t ad = abase + (wr * 64 + mi * 16 + arow) * ROWB
                            + (k0 + 8 * ahalf) * 2;
                asm volatile("ldmatrix.sync.aligned.m8n8.x4.shared.b16 "
                             "{%0,%1,%2,%3}, [%4];"
                    : "=r"(a[mi][0]), "=r"(a[mi][1]),
                      "=r"(a[mi][2]), "=r"(a[mi][3]) : "r"(ad));
            }
            // B: one x4 per pair of n8 tiles: {nj=2p k0h, nj=2p k1h, nj=2p+1 k0h, nj=2p+1 k1h}
            #pragma unroll
            for (int p = 0; p < 4; p++) {
                uint32_t bd = bbase + (wc * 64 + (2 * p + bnoff) * 8 + brow) * ROWB
                            + (k0 + 8 * bkhalf) * 2;
                asm volatile("ldmatrix.sync.aligned.m8n8.x4.shared.b16 "
                             "{%0,%1,%2,%3}, [%4];"
                    : "=r"(b[p][0]), "=r"(b[p][1]),
                      "=r"(b[p][2]), "=r"(b[p][3]) : "r"(bd));
            }
            #pragma unroll
            for (int mi = 0; mi < 4; mi++)
                #pragma unroll
                for (int nj = 0; nj < 8; nj++) {
                    int p = nj >> 1, o = (nj & 1) * 2;
                    asm volatile(
                        "mma.sync.aligned.m16n8k16.row.col.f32.bf16.bf16.f32 "
                        "{%0,%1,%2,%3}, {%4,%5,%6,%7}, {%8,%9}, {%0,%1,%2,%3};"
                        : "+f"(acc[mi][nj][0]), "+f"(acc[mi][nj][1]),
                          "+f"(acc[mi][nj][2]), "+f"(acc[mi][nj][3])
                        : "r"(a[mi][0]), "r"(a[mi][1]),
                          "r"(a[mi][2]), "r"(a[mi][3]),
                          "r"(b[p][o]), "r"(b[p][o + 1]));
                }
        }
        __syncthreads();
    }

    // ---- fused epilogue ----
    float* pMs = (float*)(smem + SM_RED);   // [128][2]
    float* pSs = pMs + 256;
    int r4 = lane >> 2;
    #pragma unroll
    for (int mi = 0; mi < 4; mi++) {
        #pragma unroll
        for (int half = 0; half < 2; half++) {
            float m = -1e30f;
            #pragma unroll
            for (int nj = 0; nj < 8; nj++) {
                m = fmaxf(m, acc[mi][nj][half * 2]);
                m = fmaxf(m, acc[mi][nj][half * 2 + 1]);
            }
            m = fmaxf(m, __shfl_xor_sync(0xffffffffu, m, 1));
            m = fmaxf(m, __shfl_xor_sync(0xffffffffu, m, 2));
            float s = 0.f;
            #pragma unroll
            for (int nj = 0; nj < 8; nj++)
                s += __expf(acc[mi][nj][half * 2] - m)
                   + __expf(acc[mi][nj][half * 2 + 1] - m);
            s += __shfl_xor_sync(0xffffffffu, s, 1);
            s += __shfl_xor_sync(0xffffffffu, s, 2);
            if ((lane & 3) == 0) {
                int lr = wr * 64 + mi * 16 + half * 8 + r4;
                pMs[lr * 2 + wc] = m;
                pSs[lr * 2 + wc] = s;
            }
        }
    }
    if (rb == cb) {
        int c2 = (lane & 3) * 2;
        #pragma unroll
        for (int mi = 0; mi < 4; mi++)
            #pragma unroll
            for (int nj = 0; nj < 8; nj++)
                #pragma unroll
                for (int q = 0; q < 4; q++) {
                    int lr = wr * 64 + mi * 16 + (q >> 1) * 8 + r4;
                    int lc = wc * 64 + nj * 8 + c2 + (q & 1);
                    if (lr == lc) g_diag[rb * 128 + lr] = acc[mi][nj][q];
                }
    }
    __syncthreads();
    {
        float M = fmaxf(pMs[tid * 2], pMs[tid * 2 + 1]);
        float S = pSs[tid * 2]     * __expf(pMs[tid * 2]     - M)
                + pSs[tid * 2 + 1] * __expf(pMs[tid * 2 + 1] - M);
        int grow = rb * 128 + tid;
        g_pM[cb * B_TOT + grow] = M;
        g_pS[cb * B_TOT + grow] = S;
    }
}

// ---------------- K5: combine partials + per-block double sum -------------
__global__ void __launch_bounds__(128) k_combine() {
    __shared__ double red[128];
    int tid = threadIdx.x;
    int i = blockIdx.x * 128 + tid;
    float M = -1e30f;
    #pragma unroll
    for (int p = 0; p < 32; p++) M = fmaxf(M, g_pM[p * B_TOT + i]);
    float S = 0.f;
    #pragma unroll
    for (int p = 0; p < 32; p++)
        S += g_pS[p * B_TOT + i] * __expf(g_pM[p * B_TOT + i] - M);
    red[tid] = (double)(M + logf(S) - g_diag[i]);
    __syncthreads();
    for (int s = 64; s > 0; s >>= 1) {
        if (tid < s) red[tid] += red[tid + s];
        __syncthreads();
    }
    if (tid == 0) g_bsum[blockIdx.x] = red[0];
}

// ---------------- K6: final 32-way sum ------------------------------------
__global__ void k_final(float* __restrict__ out) {
    if (threadIdx.x == 0) {
        double s = 0.0;
        #pragma unroll
        for (int i = 0; i < 32; i++) s += g_bsum[i];
        out[0] = (float)(s / 4096.0);
    }
}

extern "C" void kernel_launch(void* const* d_in, const int* in_sizes, int n_in,
                              void* d_out, int out_size) {
    const float* zw0  = (const float*)d_in[0];
    const float* zw1  = (const float*)d_in[1];
    const float* c    = (const float*)d_in[2];
    const float* Wkw  = (const float*)d_in[3];
    const float* Wkb  = (const float*)d_in[4];
    const float* Ww0w = (const float*)d_in[5];
    const float* Ww0b = (const float*)d_in[6];
    const float* Ww1w = (const float*)d_in[7];
    const float* Ww1b = (const float*)d_in[8];
    const float* l0w  = (const float*)d_in[9];
    const float* l0b  = (const float*)d_in[10];
    const float* l1w  = (const float*)d_in[11];
    const float* l1b  = (const float*)d_in[12];
    const float* a01w = (const float*)d_in[13];
    const float* a01b = (const float*)d_in[14];
    const float* a02w = (const float*)d_in[15];
    const float* a02b = (const float*)d_in[16];
    const float* a11w = (const float*)d_in[17];
    const float* a11b = (const float*)d_in[18];
    const float* a12w = (const float*)d_in[19];
    const float* a12b = (const float*)d_in[20];
    float* out = (float*)d_out;

    int predsm = (2 * 128 * PAD + 128 + 64 + 128 + 128) * 4;
    cudaFuncSetAttribute(k_pred_gemm, cudaFuncAttributeMaxDynamicSharedMemorySize,
                         predsm);
    cudaFuncSetAttribute(k_gemm_mma, cudaFuncAttributeMaxDynamicSharedMemorySize,
                         GSMEM);

    k_zt_s<<<512, 128>>>(zw0, zw1, l0w, l0b, l1w, l1b,
                         a01w, a01b, a02w, a02b, a11w, a11b, a12w, a12b);
    k_stats2<<<2, 1024>>>();
    k_pred_gemm<<<32, 256, predsm>>>(c, Wkw, Wkb, Ww0w, Ww0b, Ww1w, Ww1b);
    k_gemm_mma<<<dim3(32, 32), 128, GSMEM>>>();
    k_combine<<<32, 128>>>();
    k_final<<<1, 32>>>(out);
}

// round 13
// speedup vs baseline: 1.2359x; 1.2160x over previous
#include <cuda_runtime.h>
#include <cuda_bf16.h>
#include <cstdint>

#define B_TOT 4096
#define B_HALF 2048
#define PAD 130

// ---------------- device scratch ----------------
__device__ float g_zt[B_TOT * 64];
__device__ float g_s[B_TOT];
__device__ float g_e[B_TOT];
__device__ float g_T[2];
__device__ float g_Zp[32 * 64];
__device__ float g_diag[B_TOT];
__device__ float g_pM[32 * B_TOT];
__device__ float g_pS[32 * B_TOT];
__device__ double g_bsum[32];
__device__ __align__(16) unsigned short g_A[B_TOT * 384];  // bf16 [hi|lo|hi]
__device__ __align__(16) unsigned short g_B[B_TOT * 384];  // bf16 [hi|hi|lo]

__device__ __forceinline__ uint32_t smem_u32(const void* p) {
    uint32_t a;
    asm("{ .reg .u64 t; cvta.to.shared.u64 t, %1; cvt.u32.u64 %0, t; }"
        : "=r"(a) : "l"(p));
    return a;
}
__device__ __forceinline__ void ffma2(unsigned long long& d,
                                      unsigned long long a,
                                      unsigned long long b) {
    asm("fma.rn.f32x2 %0, %1, %2, %0;" : "+l"(d) : "l"(a), "l"(b));
}

// ---------------- K1: zt/score + A-side bf16 split ------------------------
__global__ void __launch_bounds__(128) k_zt_s(
    const float* __restrict__ zw0, const float* __restrict__ zw1,
    const float* __restrict__ l0w, const float* __restrict__ l0b,
    const float* __restrict__ l1w, const float* __restrict__ l1b,
    const float* __restrict__ a01w, const float* __restrict__ a01b,
    const float* __restrict__ a02w, const float* __restrict__ a02b,
    const float* __restrict__ a11w, const float* __restrict__ a11b,
    const float* __restrict__ a12w, const float* __restrict__ a12b)
{
    __shared__ float lw_s[64 * 132];
    __shared__ float awT[64 * 32];
    __shared__ float lb_s[64], ab_s[32], a2_s[32];
    __shared__ float zw_s[2][128];
    __shared__ float zt_s[2][64];
    __shared__ float a2b_s;
    int tid = threadIdx.x;
    int row0 = blockIdx.x * 8;
    int g = (row0 >= B_HALF);
    const float* zw  = g ? (zw1 + (row0 - B_HALF) * 128) : (zw0 + row0 * 128);
    const float* lw  = g ? l1w : l0w;
    const float* lb  = g ? l1b : l0b;
    const float* a1w = g ? a11w : a01w;
    const float* a1b = g ? a11b : a01b;
    const float* a2w = g ? a12w : a02w;
    const float* a2b = g ? a12b : a02b;

    for (int n = tid; n < 1024; n += 128) {
        int r = n >> 7, col = n & 127;
        float x = zw[r * 128 + col];
        __nv_bfloat16 h = __float2bfloat16(x);
        __nv_bfloat16 l = __float2bfloat16(x - __bfloat162float(h));
        unsigned short hu = __bfloat16_as_ushort(h);
        unsigned short lu = __bfloat16_as_ushort(l);
        unsigned short* Ad = g_A + (size_t)(row0 + r) * 384;
        Ad[col] = hu; Ad[128 + col] = lu; Ad[256 + col] = hu;
    }

    for (int n = tid; n < 2048; n += 128) {
        float4 v = ((const float4*)lw)[n];
        int t = n >> 5; int k4 = (n & 31) * 4;
        *((float4*)&lw_s[t * 132 + k4]) = v;
    }
    for (int n = tid; n < 512; n += 128) {
        float4 v = ((const float4*)a1w)[n];
        int t = n >> 4; int k = (n & 15) * 4;
        awT[(k + 0) * 32 + t] = v.x; awT[(k + 1) * 32 + t] = v.y;
        awT[(k + 2) * 32 + t] = v.z; awT[(k + 3) * 32 + t] = v.w;
    }
    if (tid < 64) lb_s[tid] = lb[tid];
    if (tid < 32) { ab_s[tid] = a1b[tid]; a2_s[tid] = a2w[tid]; }
    if (tid == 0) a2b_s = a2b[0];
    __syncthreads();

    for (int rp = 0; rp < 8; rp += 2) {
        ((float*)zw_s)[tid]       = zw[rp * 128 + tid];
        ((float*)zw_s)[tid + 128] = zw[rp * 128 + tid + 128];
        __syncthreads();
        int t = tid & 63, rs = tid >> 6;
        // 4 rotating accumulators to break the FFMA RAW chain
        float ac0 = lb_s[t], ac1 = 0.f, ac2v = 0.f, ac3 = 0.f;
        #pragma unroll
        for (int k = 0; k < 128; k += 16) {
            float4 w0 = *((const float4*)&lw_s[t * 132 + k]);
            float4 z0 = *((const float4*)&zw_s[rs][k]);
            ac0 += w0.x * z0.x + w0.y * z0.y + w0.z * z0.z + w0.w * z0.w;
            float4 w1 = *((const float4*)&lw_s[t * 132 + k + 4]);
            float4 z1 = *((const float4*)&zw_s[rs][k + 4]);
            ac1 += w1.x * z1.x + w1.y * z1.y + w1.z * z1.z + w1.w * z1.w;
            float4 w2 = *((const float4*)&lw_s[t * 132 + k + 8]);
            float4 z2 = *((const float4*)&zw_s[rs][k + 8]);
            ac2v += w2.x * z2.x + w2.y * z2.y + w2.z * z2.z + w2.w * z2.w;
            float4 w3 = *((const float4*)&lw_s[t * 132 + k + 12]);
            float4 z3 = *((const float4*)&zw_s[rs][k + 12]);
            ac3 += w3.x * z3.x + w3.y * z3.y + w3.z * z3.z + w3.w * z3.w;
        }
        float zt = fmaxf((ac0 + ac1) + (ac2v + ac3), 0.0f);
        zt_s[rs][t] = zt;
        g_zt[(row0 + rp + rs) * 64 + t] = zt;
        __syncthreads();
        if (tid < 64) {
            int r = tid >> 5, j = tid & 31;
            float h = ab_s[j];
            #pragma unroll
            for (int k = 0; k < 64; k++) h += zt_s[r][k] * awT[k * 32 + j];
            h = tanhf(h);
            float v = h * a2_s[j];
            #pragma unroll
            for (int o = 16; o; o >>= 1) v += __shfl_xor_sync(0xffffffffu, v, o);
            if (j == 0) g_s[row0 + rp + r] = v + a2b_s;
        }
        __syncthreads();
    }
}

// ---------------- K2: per-group m, e, T ----------------
__global__ void __launch_bounds__(1024) k_stats() {
    __shared__ float red[1024];
    int g = blockIdx.x;
    int base = g * B_HALF;
    int tid = threadIdx.x;
    float s0 = g_s[base + tid], s1 = g_s[base + tid + 1024];
    float m = fmaxf(s0, s1);
    red[tid] = m; __syncthreads();
    for (int s = 512; s > 0; s >>= 1) {
        if (tid < s) red[tid] = fmaxf(red[tid], red[tid + s]);
        __syncthreads();
    }
    m = red[0];
    __syncthreads();
    float e0 = __expf(s0 - m);
    float e1 = __expf(s1 - m);
    g_e[base + tid] = e0; g_e[base + tid + 1024] = e1;
    red[tid] = e0 + e1; __syncthreads();
    for (int s = 512; s > 0; s >>= 1) {
        if (tid < s) red[tid] += red[tid + s];
        __syncthreads();
    }
    if (tid == 0) g_T[g] = red[0];
}

// ---------------- K2b: partial Z over 128-row chunks (parallel) -----------
__global__ void __launch_bounds__(256) k_zpart() {
    __shared__ float red[256];
    int b = blockIdx.x;
    int base = b * 128;
    int d = threadIdx.x & 63, sub = threadIdx.x >> 6;
    float z = 0.f;
    #pragma unroll 4
    for (int r = sub; r < 128; r += 4)
        z += g_e[base + r] * g_zt[(base + r) * 64 + d];
    red[threadIdx.x] = z;
    __syncthreads();
    if (sub == 0)
        g_Zp[b * 64 + d] = red[d] + red[64 + d] + red[128 + d] + red[192 + d];
}

// ---------------- K3: build u + pred GEMM + bf16 B-split ------------------
// 128 blocks x 128 threads; 32x128 output tile per block, K=128 (FFMA2).
__global__ void __launch_bounds__(128) k_pred_gemm(
    const float* __restrict__ c,
    const float* __restrict__ Wkw, const float* __restrict__ Wkb,
    const float* __restrict__ Ww0w, const float* __restrict__ Ww0b,
    const float* __restrict__ Ww1w, const float* __restrict__ Ww1b)
{
    extern __shared__ float sm[];
    float* Ws   = sm;                      // [128 j][130 k]
    float* As   = sm + 128 * PAD;          // [32 r][130 k]
    float* bias = As + 32 * PAD;           // [128]
    float* Zs   = bias + 128;              // [64]
    float* es   = Zs + 64;                 // [32]
    float* invs = es + 32;                 // [32]
    int tid = threadIdx.x;
    int row0 = blockIdx.x * 32;
    int g = (row0 >= B_HALF);
    const float* Ww = g ? Ww1w : Ww0w;
    const float* Wb = g ? Ww1b : Ww0b;

    for (int n = tid; n < 4096; n += 128) {
        int j = n >> 5, q = n & 31;
        float4 w; int off;
        if (q < 16) { w = ((const float4*)Ww)[j * 16 + q];         off = q * 4; }
        else        { w = ((const float4*)Wkw)[j * 16 + (q - 16)]; off = 64 + (q - 16) * 4; }
        *(float2*)&Ws[j * PAD + off]     = make_float2(w.x, w.y);
        *(float2*)&Ws[j * PAD + off + 2] = make_float2(w.z, w.w);
    }
    if (tid < 128) bias[tid] = Wb[tid] + Wkb[tid];
    if (tid < 64) {
        float z = 0.f;
        #pragma unroll
        for (int p = 0; p < 16; p++) z += g_Zp[(g * 16 + p) * 64 + tid];
        Zs[tid] = z;
    }
    if (tid < 32) {
        float e = g_e[row0 + tid];
        es[tid] = e;
        invs[tid] = 1.0f / (g_T[g] - e);
    }
    __syncthreads();

    // build u = [pooled | c] rows row0..row0+31 into As
    for (int n = tid; n < 1024; n += 128) {
        int r = n >> 5, c4 = (n & 31) * 4;
        float4 v;
        if (c4 < 64) {
            float4 zt4 = *(const float4*)&g_zt[(row0 + r) * 64 + c4];
            float e = es[r], inv = invs[r];
            v.x = (Zs[c4 + 0] - e * zt4.x) * inv;
            v.y = (Zs[c4 + 1] - e * zt4.y) * inv;
            v.z = (Zs[c4 + 2] - e * zt4.z) * inv;
            v.w = (Zs[c4 + 3] - e * zt4.w) * inv;
        } else {
            v = *(const float4*)&c[(row0 + r) * 64 + (c4 - 64)];
        }
        *(float2*)&As[r * PAD + c4]     = make_float2(v.x, v.y);
        *(float2*)&As[r * PAD + c4 + 2] = make_float2(v.z, v.w);
    }
    __syncthreads();

    int tx = tid & 15, ty = tid >> 4;       // rows ty+8i (i<4), cols tx+16j (j<8)
    unsigned long long acc2[4][8];
    #pragma unroll
    for (int i = 0; i < 4; i++)
        #pragma unroll
        for (int j = 0; j < 8; j++) acc2[i][j] = 0ull;
    #pragma unroll 2
    for (int k = 0; k < 128; k += 2) {
        unsigned long long a[4], b[8];
        #pragma unroll
        for (int i = 0; i < 4; i++)
            a[i] = *((const unsigned long long*)&As[(ty + 8 * i) * PAD + k]);
        #pragma unroll
        for (int j = 0; j < 8; j++)
            b[j] = *((const unsigned long long*)&Ws[(tx + 16 * j) * PAD + k]);
        #pragma unroll
        for (int i = 0; i < 4; i++)
            #pragma unroll
            for (int j = 0; j < 8; j++)
                ffma2(acc2[i][j], a[i], b[j]);
    }
    #pragma unroll
    for (int i = 0; i < 4; i++) {
        int row = row0 + ty + 8 * i;
        #pragma unroll
        for (int j = 0; j < 8; j++) {
            int col = tx + 16 * j;
            unsigned long long u = acc2[i][j];
            float lo = __uint_as_float((unsigned)u);
            float hi = __uint_as_float((unsigned)(u >> 32));
            float p = lo + hi + bias[col];
            __nv_bfloat16 h = __float2bfloat16(p);
            __nv_bfloat16 l = __float2bfloat16(p - __bfloat162float(h));
            unsigned short hu = __bfloat16_as_ushort(h);
            unsigned short lu = __bfloat16_as_ushort(l);
            unsigned short* Bd = g_B + (size_t)row * 384;
            Bd[col] = hu; Bd[128 + col] = hu; Bd[256 + col] = lu;
        }
    }
}

// ---------------- K4: HMMA bf16 GEMM (K'=384) + fused LSE partials -------
// 128x128 block tile, 4 warps of 64x64, mma.m16n8k16, cp.async double buffer.
#define KC 64
#define NCHUNK 6
#define ROWB 144
#define ABUF 18432
#define SM_A0 0
#define SM_B0 36864
#define SM_RED 73728
#define GSMEM (73728 + 2048)

__global__ void __launch_bounds__(128, 2) k_gemm_mma() {
    extern __shared__ __align__(128) char smem[];
    uint32_t sb = smem_u32(smem);
    int tid = threadIdx.x, wid = tid >> 5, lane = tid & 31;
    int cb = blockIdx.x, rb = blockIdx.y;
    int wr = wid >> 1, wc = wid & 1;
    const unsigned short* asrc = g_A + (size_t)rb * 128 * 384;
    const unsigned short* bsrc = g_B + (size_t)cb * 128 * 384;

    float acc[4][8][4];
    #pragma unroll
    for (int i = 0; i < 4; i++)
        #pragma unroll
        for (int j = 0; j < 8; j++)
            #pragma unroll
            for (int q = 0; q < 4; q++) acc[i][j][q] = 0.f;

    #define PREFETCH(c, buf) do {                                              \
        const unsigned short* _ap = asrc + (c) * KC;                           \
        const unsigned short* _bp = bsrc + (c) * KC;                           \
        _Pragma("unroll")                                                      \
        for (int _i = 0; _i < 8; _i++) {                                       \
            int _idx = tid + _i * 128;                                         \
            int _row = _idx >> 3, _kc = _idx & 7;                              \
            uint32_t _da = sb + SM_A0 + (buf) * ABUF + _row * ROWB + _kc * 16; \
            asm volatile("cp.async.cg.shared.global [%0], [%1], 16;"           \
                :: "r"(_da), "l"(_ap + _row * 384 + _kc * 8));                 \
            uint32_t _db = sb + SM_B0 + (buf) * ABUF + _row * ROWB + _kc * 16; \
            asm volatile("cp.async.cg.shared.global [%0], [%1], 16;"           \
                :: "r"(_db), "l"(_bp + _row * 384 + _kc * 8));                 \
        }                                                                      \
        asm volatile("cp.async.commit_group;");                                \
    } while (0)

    int arow = lane & 15, ahalf = lane >> 4;
    int bnoff = (lane >> 4) & 1;
    int bkhalf = (lane >> 3) & 1;
    int brow = lane & 7;

    PREFETCH(0, 0);
    for (int c = 0; c < NCHUNK; c++) {
        int buf = c & 1;
        if (c + 1 < NCHUNK) {
            PREFETCH(c + 1, buf ^ 1);
            asm volatile("cp.async.wait_group 1;");
        } else {
            asm volatile("cp.async.wait_group 0;");
        }
        __syncthreads();
        uint32_t abase = sb + SM_A0 + buf * ABUF;
        uint32_t bbase = sb + SM_B0 + buf * ABUF;
        #pragma unroll
        for (int k0 = 0; k0 < KC; k0 += 16) {
            uint32_t a[4][4], b[4][4];
            #pragma unroll
            for (int mi = 0; mi < 4; mi++) {
                uint32_t ad = abase + (wr * 64 + mi * 16 + arow) * ROWB
                            + (k0 + 8 * ahalf) * 2;
                asm volatile("ldmatrix.sync.aligned.m8n8.x4.shared.b16 "
                             "{%0,%1,%2,%3}, [%4];"
                    : "=r"(a[mi][0]), "=r"(a[mi][1]),
                      "=r"(a[mi][2]), "=r"(a[mi][3]) : "r"(ad));
            }
            #pragma unroll
            for (int p = 0; p < 4; p++) {
                uint32_t bd = bbase + (wc * 64 + (2 * p + bnoff) * 8 + brow) * ROWB
                            + (k0 + 8 * bkhalf) * 2;
                asm volatile("ldmatrix.sync.aligned.m8n8.x4.shared.b16 "
                             "{%0,%1,%2,%3}, [%4];"
                    : "=r"(b[p][0]), "=r"(b[p][1]),
                      "=r"(b[p][2]), "=r"(b[p][3]) : "r"(bd));
            }
            #pragma unroll
            for (int mi = 0; mi < 4; mi++)
                #pragma unroll
                for (int nj = 0; nj < 8; nj++) {
                    int p = nj >> 1, o = (nj & 1) * 2;
                    asm volatile(
                        "mma.sync.aligned.m16n8k16.row.col.f32.bf16.bf16.f32 "
                        "{%0,%1,%2,%3}, {%4,%5,%6,%7}, {%8,%9}, {%0,%1,%2,%3};"
                        : "+f"(acc[mi][nj][0]), "+f"(acc[mi][nj][1]),
                          "+f"(acc[mi][nj][2]), "+f"(acc[mi][nj][3])
                        : "r"(a[mi][0]), "r"(a[mi][1]),
                          "r"(a[mi][2]), "r"(a[mi][3]),
                          "r"(b[p][o]), "r"(b[p][o + 1]));
                }
        }
        __syncthreads();
    }

    float* pMs = (float*)(smem + SM_RED);
    float* pSs = pMs + 256;
    int r4 = lane >> 2;
    #pragma unroll
    for (int mi = 0; mi < 4; mi++) {
        #pragma unroll
        for (int half = 0; half < 2; half++) {
            float m = -1e30f;
            #pragma unroll
            for (int nj = 0; nj < 8; nj++) {
                m = fmaxf(m, acc[mi][nj][half * 2]);
                m = fmaxf(m, acc[mi][nj][half * 2 + 1]);
            }
            m = fmaxf(m, __shfl_xor_sync(0xffffffffu, m, 1));
            m = fmaxf(m, __shfl_xor_sync(0xffffffffu, m, 2));
            float s = 0.f;
            #pragma unroll
            for (int nj = 0; nj < 8; nj++)
                s += __expf(acc[mi][nj][half * 2] - m)
                   + __expf(acc[mi][nj][half * 2 + 1] - m);
            s += __shfl_xor_sync(0xffffffffu, s, 1);
            s += __shfl_xor_sync(0xffffffffu, s, 2);
            if ((lane & 3) == 0) {
                int lr = wr * 64 + mi * 16 + half * 8 + r4;
                pMs[lr * 2 + wc] = m;
                pSs[lr * 2 + wc] = s;
            }
        }
    }
    if (rb == cb) {
        int c2 = (lane & 3) * 2;
        #pragma unroll
        for (int mi = 0; mi < 4; mi++)
            #pragma unroll
            for (int nj = 0; nj < 8; nj++)
                #pragma unroll
                for (int q = 0; q < 4; q++) {
                    int lr = wr * 64 + mi * 16 + (q >> 1) * 8 + r4;
                    int lc = wc * 64 + nj * 8 + c2 + (q & 1);
                    if (lr == lc) g_diag[rb * 128 + lr] = acc[mi][nj][q];
                }
    }
    __syncthreads();
    {
        float M = fmaxf(pMs[tid * 2], pMs[tid * 2 + 1]);
        float S = pSs[tid * 2]     * __expf(pMs[tid * 2]     - M)
                + pSs[tid * 2 + 1] * __expf(pMs[tid * 2 + 1] - M);
        int grow = rb * 128 + tid;
        g_pM[cb * B_TOT + grow] = M;
        g_pS[cb * B_TOT + grow] = S;
    }
}

// ---------------- K5: combine partials + per-block double sum -------------
__global__ void __launch_bounds__(128) k_combine() {
    __shared__ double red[128];
    int tid = threadIdx.x;
    int i = blockIdx.x * 128 + tid;
    float M = -1e30f;
    #pragma unroll
    for (int p = 0; p < 32; p++) M = fmaxf(M, g_pM[p * B_TOT + i]);
    float S = 0.f;
    #pragma unroll
    for (int p = 0; p < 32; p++)
        S += g_pS[p * B_TOT + i] * __expf(g_pM[p * B_TOT + i] - M);
    red[tid] = (double)(M + logf(S) - g_diag[i]);
    __syncthreads();
    for (int s = 64; s > 0; s >>= 1) {
        if (tid < s) red[tid] += red[tid + s];
        __syncthreads();
    }
    if (tid == 0) g_bsum[blockIdx.x] = red[0];
}

// ---------------- K6: final 32-way sum ------------------------------------
__global__ void k_final(float* __restrict__ out) {
    if (threadIdx.x == 0) {
        double s = 0.0;
        #pragma unroll
        for (int i = 0; i < 32; i++) s += g_bsum[i];
        out[0] = (float)(s / 4096.0);
    }
}

extern "C" void kernel_launch(void* const* d_in, const int* in_sizes, int n_in,
                              void* d_out, int out_size) {
    const float* zw0  = (const float*)d_in[0];
    const float* zw1  = (const float*)d_in[1];
    const float* c    = (const float*)d_in[2];
    const float* Wkw  = (const float*)d_in[3];
    const float* Wkb  = (const float*)d_in[4];
    const float* Ww0w = (const float*)d_in[5];
    const float* Ww0b = (const float*)d_in[6];
    const float* Ww1w = (const float*)d_in[7];
    const float* Ww1b = (const float*)d_in[8];
    const float* l0w  = (const float*)d_in[9];
    const float* l0b  = (const float*)d_in[10];
    const float* l1w  = (const float*)d_in[11];
    const float* l1b  = (const float*)d_in[12];
    const float* a01w = (const float*)d_in[13];
    const float* a01b = (const float*)d_in[14];
    const float* a02w = (const float*)d_in[15];
    const float* a02b = (const float*)d_in[16];
    const float* a11w = (const float*)d_in[17];
    const float* a11b = (const float*)d_in[18];
    const float* a12w = (const float*)d_in[19];
    const float* a12b = (const float*)d_in[20];
    float* out = (float*)d_out;

    int predsm = (128 * PAD + 32 * PAD + 128 + 64 + 32 + 32) * 4;
    cudaFuncSetAttribute(k_pred_gemm, cudaFuncAttributeMaxDynamicSharedMemorySize,
                         predsm);
    cudaFuncSetAttribute(k_gemm_mma, cudaFuncAttributeMaxDynamicSharedMemorySize,
                         GSMEM);

    k_zt_s<<<512, 128>>>(zw0, zw1, l0w, l0b, l1w, l1b,
                         a01w, a01b, a02w, a02b, a11w, a11b, a12w, a12b);
    k_stats<<<2, 1024>>>();
    k_zpart<<<32, 256>>>();
    k_pred_gemm<<<128, 128, predsm>>>(c, Wkw, Wkb, Ww0w, Ww0b, Ww1w, Ww1b);
    k_gemm_mma<<<dim3(32, 32), 128, GSMEM>>>();
    k_combine<<<32, 128>>>();
    k_final<<<1, 32>>>(out);
}